// round 9
// baseline (speedup 1.0000x reference)
#include <cuda_runtime.h>
#include <cuda_fp16.h>
#include <math.h>

#define NMAX 100000
#define EMAX 3200000
#define CSRMAX (EMAX + 3 * NMAX + 32)
#define HID  64
#define MHID 128
#define KOUT 15
#define SCAN_BS 1024
#define NBMAX ((NMAX + SCAN_BS - 1) / SCAN_BS)

// ---- device-global scratch (no allocations allowed) ----
__device__ __half g_ah[(NMAX + 1) * HID];  // fp16 pre-scaled messages; row n = zeros
__device__ float  g_b[NMAX * HID];         // aggregated output / GEMM input (fp32)
__device__ float  g_dis[NMAX];             // (deg+1)^{-1/2}
__device__ int    g_deg[NMAX];
__device__ int    g_off[NMAX + 1];         // CSR row offsets (padded to x4)
__device__ int    g_rank[EMAX];            // rank of edge within its dst row
__device__ int    g_csr[CSRMAX];           // CSR src indices (padded with n)
__device__ int    g_bsum[NBMAX];
__device__ int    g_bar;                   // device-wide barrier counter

__device__ __forceinline__ float eluf(float v) { return v > 0.f ? v : expm1f(v); }

__device__ __forceinline__ float4 h4tof4(uint2 v) {
    float2 a = __half22float2(*reinterpret_cast<__half2*>(&v.x));
    float2 b = __half22float2(*reinterpret_cast<__half2*>(&v.y));
    return make_float4(a.x, a.y, b.x, b.y);
}

// ------------------------- degree count + edge rank (atomic return reused)
__global__ void k_deg_rank(const int* __restrict__ ei, int E) {
    int t = blockIdx.x * blockDim.x + threadIdx.x;
    if (t == 0) g_bar = 0;                 // reset scan barrier for this launch
    int E8 = E >> 3;
    if (t < E8) {
        int4 d0 = reinterpret_cast<const int4*>(ei + E)[2 * t];
        int4 d1 = reinterpret_cast<const int4*>(ei + E)[2 * t + 1];
        int4 r0, r1;
        r0.x = atomicAdd(&g_deg[d0.x], 1);
        r0.y = atomicAdd(&g_deg[d0.y], 1);
        r0.z = atomicAdd(&g_deg[d0.z], 1);
        r0.w = atomicAdd(&g_deg[d0.w], 1);
        r1.x = atomicAdd(&g_deg[d1.x], 1);
        r1.y = atomicAdd(&g_deg[d1.y], 1);
        r1.z = atomicAdd(&g_deg[d1.z], 1);
        r1.w = atomicAdd(&g_deg[d1.w], 1);
        reinterpret_cast<int4*>(g_rank)[2 * t]     = r0;
        reinterpret_cast<int4*>(g_rank)[2 * t + 1] = r1;
    } else {
        int e = E8 * 8 + (t - E8);
        if (e < E) g_rank[e] = atomicAdd(&g_deg[ei[E + e]], 1);
    }
}

// ---------------- fused exclusive scan + offsets/dis/dummy fill
// grid = nb (<= 98 blocks, all resident) x 1024 threads; device-wide barrier.
__global__ void k_scan(int n, int nb) {
    __shared__ int s[SCAN_BS];
    int t = threadIdx.x;
    int b = blockIdx.x;
    int i = b * SCAN_BS + t;
    int deg = (i < n) ? g_deg[i] : 0;
    int pdeg = (deg + 3) & ~3;
    int v = pdeg;
    s[t] = v;
    __syncthreads();
#pragma unroll
    for (int off = 1; off < SCAN_BS; off <<= 1) {
        int add = (t >= off) ? s[t - off] : 0;
        __syncthreads();
        s[t] += add;
        __syncthreads();
    }
    int exc = s[t] - v;                     // intra-block exclusive

    if (t == 0) {
        g_bsum[b] = s[SCAN_BS - 1];
        __threadfence();
        atomicAdd(&g_bar, 1);
        while (atomicAdd(&g_bar, 0) < nb) __nanosleep(64);
    }
    __syncthreads();
    __threadfence();

    s[t] = (t < b) ? g_bsum[t] : 0;
    __syncthreads();
#pragma unroll
    for (int off = SCAN_BS / 2; off > 0; off >>= 1) {
        if (t < off) s[t] += s[t + off];
        __syncthreads();
    }
    int off = s[0] + exc;

    if (i < n) {
        g_off[i] = off;
        g_dis[i] = rsqrtf((float)(deg + 1));
        for (int j = deg; j < pdeg; j++) g_csr[off + j] = n;  // dummy -> zero row
        if (i == n - 1) {
            int total = off + pdeg;
            g_off[n] = total;
            for (int j = 0; j < 16; j++) g_csr[total + j] = n;  // prefetch slack
        }
    }
}

// ------------------------------- scatter (no atomics: rank precomputed)
__global__ void k_scatter(const int* __restrict__ ei, int E) {
    int t = blockIdx.x * blockDim.x + threadIdx.x;
    int E8 = E >> 3;
    if (t < E8) {
        int4 s0 = reinterpret_cast<const int4*>(ei)[2 * t];
        int4 s1 = reinterpret_cast<const int4*>(ei)[2 * t + 1];
        int4 d0 = reinterpret_cast<const int4*>(ei + E)[2 * t];
        int4 d1 = reinterpret_cast<const int4*>(ei + E)[2 * t + 1];
        int4 r0 = reinterpret_cast<const int4*>(g_rank)[2 * t];
        int4 r1 = reinterpret_cast<const int4*>(g_rank)[2 * t + 1];
        int o0 = g_off[d0.x], o1 = g_off[d0.y], o2 = g_off[d0.z], o3 = g_off[d0.w];
        int o4 = g_off[d1.x], o5 = g_off[d1.y], o6 = g_off[d1.z], o7 = g_off[d1.w];
        g_csr[o0 + r0.x] = s0.x;
        g_csr[o1 + r0.y] = s0.y;
        g_csr[o2 + r0.z] = s0.z;
        g_csr[o3 + r0.w] = s0.w;
        g_csr[o4 + r1.x] = s1.x;
        g_csr[o5 + r1.y] = s1.y;
        g_csr[o6 + r1.z] = s1.z;
        g_csr[o7 + r1.w] = s1.w;
    } else {
        int e = E8 * 8 + (t - E8);
        if (e < E) g_csr[g_off[ei[E + e]] + g_rank[e]] = ei[e];
    }
}

// ------------------------------------------- layer-1 input GEMM (3 -> 64)
__global__ void k_hw1(const float* __restrict__ x, const float* __restrict__ W1, int n) {
    int idx = blockIdx.x * blockDim.x + threadIdx.x;   // over (n+1)*32
    if (idx >= (n + 1) * 32) return;
    int i = idx >> 5, f = (idx & 31) * 2;
    __half2* a2 = reinterpret_cast<__half2*>(g_ah);
    if (i == n) { a2[idx] = __floats2half2_rn(0.f, 0.f); return; }
    float x0 = x[i * 3 + 0], x1 = x[i * 3 + 1], x2 = x[i * 3 + 2];
    float d = g_dis[i];
    float v0 = (x0 * W1[f]     + x1 * W1[HID + f]     + x2 * W1[2 * HID + f]) * d;
    float v1 = (x0 * W1[f + 1] + x1 * W1[HID + f + 1] + x2 * W1[2 * HID + f + 1]) * d;
    a2[idx] = __floats2half2_rn(v0, v1);
}

// --------------------------------------------- CSR aggregation (hot, x2)
// warp per node; paired gathers (lanes 0-15 even edges, 16-31 odd edges);
// HADD2 4-term chunks; software-pipelined index prefetch (slack-padded CSR).
__global__ void k_aggr(int n) {
    int gw = (blockIdx.x * blockDim.x + threadIdx.x) >> 5;
    if (gw >= n) return;
    int lane = threadIdx.x & 31;
    const uint2* __restrict__ ah4 = reinterpret_cast<const uint2*>(g_ah);
    int half_ = lane >> 4;          // 0 or 1
    int fo = lane & 15;             // half4 slot within row

    float4 acc = make_float4(0.f, 0.f, 0.f, 0.f);
    if (half_ == 0) acc = h4tof4(ah4[gw * 16 + fo]);   // self loop (fp32)

    int j = g_off[gw];
    int end = g_off[gw + 1];

    int4 c0, c1;
    if (j < end) {                          // over-read OK (slack-padded)
        c0 = *reinterpret_cast<const int4*>(&g_csr[j]);
        c1 = *reinterpret_cast<const int4*>(&g_csr[j + 4]);
    }
    while (j + 8 <= end) {
        // prefetch next chunk unconditionally (always in-bounds via slack)
        int4 n0 = *reinterpret_cast<const int4*>(&g_csr[j + 8]);
        int4 n1 = *reinterpret_cast<const int4*>(&g_csr[j + 12]);
        int sA = half_ ? c0.y : c0.x;
        int sB = half_ ? c0.w : c0.z;
        int sC = half_ ? c1.y : c1.x;
        int sD = half_ ? c1.w : c1.z;
        uint2 vA = ah4[sA * 16 + fo];
        uint2 vB = ah4[sB * 16 + fo];
        uint2 vC = ah4[sC * 16 + fo];
        uint2 vD = ah4[sD * 16 + fo];
        __half2 p0 = __hadd2(__hadd2(*reinterpret_cast<__half2*>(&vA.x),
                                     *reinterpret_cast<__half2*>(&vB.x)),
                             __hadd2(*reinterpret_cast<__half2*>(&vC.x),
                                     *reinterpret_cast<__half2*>(&vD.x)));
        __half2 p1 = __hadd2(__hadd2(*reinterpret_cast<__half2*>(&vA.y),
                                     *reinterpret_cast<__half2*>(&vB.y)),
                             __hadd2(*reinterpret_cast<__half2*>(&vC.y),
                                     *reinterpret_cast<__half2*>(&vD.y)));
        float2 f0 = __half22float2(p0);
        float2 f1 = __half22float2(p1);
        acc.x += f0.x; acc.y += f0.y; acc.z += f1.x; acc.w += f1.y;
        c0 = n0; c1 = n1;
        j += 8;
    }
    if (j < end) {                          // remainder exactly 4 (in c0)
        int sA = half_ ? c0.y : c0.x;
        int sB = half_ ? c0.w : c0.z;
        uint2 vA = ah4[sA * 16 + fo];
        uint2 vB = ah4[sB * 16 + fo];
        __half2 p0 = __hadd2(*reinterpret_cast<__half2*>(&vA.x),
                             *reinterpret_cast<__half2*>(&vB.x));
        __half2 p1 = __hadd2(*reinterpret_cast<__half2*>(&vA.y),
                             *reinterpret_cast<__half2*>(&vB.y));
        float2 f0 = __half22float2(p0);
        float2 f1 = __half22float2(p1);
        acc.x += f0.x; acc.y += f0.y; acc.z += f1.x; acc.w += f1.y;
    }
    acc.x += __shfl_down_sync(0xffffffffu, acc.x, 16);
    acc.y += __shfl_down_sync(0xffffffffu, acc.y, 16);
    acc.z += __shfl_down_sync(0xffffffffu, acc.z, 16);
    acc.w += __shfl_down_sync(0xffffffffu, acc.w, 16);

    if (lane < 16) {
        float d = g_dis[gw];
        *reinterpret_cast<float4*>(&g_b[gw * HID + lane * 4]) =
            make_float4(acc.x * d, acc.y * d, acc.z * d, acc.w * d);
    }
}

// ---------------------------------------- layer-2 GEMM: elu(g_b+b1) @ W2
__global__ void k_gcn_gemm64(const float* __restrict__ bias,
                             const float* __restrict__ W, int n) {
    __shared__ float As[32][HID];
    __shared__ float Ws[HID * HID];
    int tid = threadIdx.x;
    int row0 = blockIdx.x * 32;

    for (int i = tid; i < HID * HID; i += 256) Ws[i] = W[i];
    for (int i = tid; i < 32 * HID; i += 256) {
        int r = i >> 6, k = i & 63;
        int row = row0 + r;
        As[r][k] = (row < n) ? eluf(g_b[row * HID + k] + bias[k]) : 0.f;
    }
    __syncthreads();

    int fx = (tid & 15) * 4;
    int n0 = (tid >> 4) * 2;
    float4 a0c = make_float4(0.f, 0.f, 0.f, 0.f);
    float4 a1c = make_float4(0.f, 0.f, 0.f, 0.f);
#pragma unroll 16
    for (int k = 0; k < HID; k++) {
        float4 w = *reinterpret_cast<const float4*>(&Ws[k * HID + fx]);
        float a0 = As[n0][k], a1 = As[n0 + 1][k];
        a0c.x += a0 * w.x; a0c.y += a0 * w.y; a0c.z += a0 * w.z; a0c.w += a0 * w.w;
        a1c.x += a1 * w.x; a1c.y += a1 * w.y; a1c.z += a1 * w.z; a1c.w += a1 * w.w;
    }
#pragma unroll
    for (int r = 0; r < 2; r++) {
        int row = row0 + n0 + r;
        if (row >= n) continue;
        float d = g_dis[row];
        float4 acc = r ? a1c : a0c;
        __half2* a2 = reinterpret_cast<__half2*>(g_ah);
        a2[row * 32 + (fx >> 1)]     = __floats2half2_rn(acc.x * d, acc.y * d);
        a2[row * 32 + (fx >> 1) + 1] = __floats2half2_rn(acc.z * d, acc.w * d);
    }
}

// ---------------- fused MLP (32 rows/block, dynamic smem) + softmax
#define SMEM_MLP_FLOATS (32 * HID + HID * MHID + 32 * MHID + MHID * KOUT + KOUT)
__global__ void k_mlp(const float* __restrict__ b2,
                      const float* __restrict__ Wm1,
                      const float* __restrict__ bm1,
                      const float* __restrict__ Wm2,
                      const float* __restrict__ bm2,
                      float* __restrict__ out, int n) {
    extern __shared__ float sm[];
    float* As  = sm;                        // [32][64]
    float* Ws  = As + 32 * HID;             // [64][128]
    float* Hs  = Ws + HID * MHID;           // [32][128]
    float* W2s = Hs + 32 * MHID;            // [128*15]
    float* b2s = W2s + MHID * KOUT;         // [15]
    int tid = threadIdx.x;
    int row0 = blockIdx.x * 32;

    for (int i = tid; i < HID * MHID; i += 256) Ws[i] = Wm1[i];
    for (int i = tid; i < MHID * KOUT; i += 256) W2s[i] = Wm2[i];
    if (tid < KOUT) b2s[tid] = bm2[tid];
    for (int i = tid; i < 32 * HID; i += 256) {
        int r = i >> 6, k = i & 63;
        int row = row0 + r;
        As[i] = (row < n) ? eluf(g_b[row * HID + k] + b2[k]) : 0.f;
    }
    __syncthreads();

    {
        int fx = (tid & 31) * 4;
        int r0 = (tid >> 5) * 4;
        float4 a0 = make_float4(0.f, 0.f, 0.f, 0.f);
        float4 a1 = make_float4(0.f, 0.f, 0.f, 0.f);
        float4 a2 = make_float4(0.f, 0.f, 0.f, 0.f);
        float4 a3 = make_float4(0.f, 0.f, 0.f, 0.f);
#pragma unroll 8
        for (int k = 0; k < HID; k++) {
            float4 w = *reinterpret_cast<const float4*>(&Ws[k * MHID + fx]);
            float v0 = As[(r0 + 0) * HID + k];
            float v1 = As[(r0 + 1) * HID + k];
            float v2 = As[(r0 + 2) * HID + k];
            float v3 = As[(r0 + 3) * HID + k];
            a0.x += v0 * w.x; a0.y += v0 * w.y; a0.z += v0 * w.z; a0.w += v0 * w.w;
            a1.x += v1 * w.x; a1.y += v1 * w.y; a1.z += v1 * w.z; a1.w += v1 * w.w;
            a2.x += v2 * w.x; a2.y += v2 * w.y; a2.z += v2 * w.z; a2.w += v2 * w.w;
            a3.x += v3 * w.x; a3.y += v3 * w.y; a3.z += v3 * w.z; a3.w += v3 * w.w;
        }
        float4 bb = *reinterpret_cast<const float4*>(&bm1[fx]);
        *reinterpret_cast<float4*>(&Hs[(r0 + 0) * MHID + fx]) =
            make_float4(eluf(a0.x + bb.x), eluf(a0.y + bb.y), eluf(a0.z + bb.z), eluf(a0.w + bb.w));
        *reinterpret_cast<float4*>(&Hs[(r0 + 1) * MHID + fx]) =
            make_float4(eluf(a1.x + bb.x), eluf(a1.y + bb.y), eluf(a1.z + bb.z), eluf(a1.w + bb.w));
        *reinterpret_cast<float4*>(&Hs[(r0 + 2) * MHID + fx]) =
            make_float4(eluf(a2.x + bb.x), eluf(a2.y + bb.y), eluf(a2.z + bb.z), eluf(a2.w + bb.w));
        *reinterpret_cast<float4*>(&Hs[(r0 + 3) * MHID + fx]) =
            make_float4(eluf(a3.x + bb.x), eluf(a3.y + bb.y), eluf(a3.z + bb.z), eluf(a3.w + bb.w));
    }
    __syncthreads();

    int wid = tid >> 5;
    int lane = tid & 31;
#pragma unroll
    for (int rr = 0; rr < 4; rr++) {
        int r = wid * 4 + rr;
        int row = row0 + r;
        float p[KOUT];
#pragma unroll
        for (int c = 0; c < KOUT; c++) p[c] = 0.f;
#pragma unroll
        for (int jj = 0; jj < 4; jj++) {
            int k = lane + 32 * jj;
            float hv = Hs[r * MHID + k];
#pragma unroll
            for (int c = 0; c < KOUT; c++) p[c] += hv * W2s[k * KOUT + c];
        }
#pragma unroll
        for (int off = 16; off > 0; off >>= 1)
#pragma unroll
            for (int c = 0; c < KOUT; c++)
                p[c] += __shfl_xor_sync(0xffffffffu, p[c], off);

        float mx = -1e30f;
#pragma unroll
        for (int c = 0; c < KOUT; c++) { p[c] += b2s[c]; mx = fmaxf(mx, p[c]); }
        float s = 0.f;
#pragma unroll
        for (int c = 0; c < KOUT; c++) { p[c] = expf(p[c] - mx); s += p[c]; }
        float inv = 1.f / s;
        if (row < n && lane < KOUT) out[row * KOUT + lane] = p[lane] * inv;
    }
}

// ---------------------------------------------------------------- launch
extern "C" void kernel_launch(void* const* d_in, const int* in_sizes, int n_in,
                              void* d_out, int out_size) {
    const float* x   = (const float*)d_in[0];
    const int*   ei  = (const int*)  d_in[1];
    const float* W1  = (const float*)d_in[2];
    const float* b1  = (const float*)d_in[3];
    const float* W2  = (const float*)d_in[4];
    const float* b2  = (const float*)d_in[5];
    const float* Wm1 = (const float*)d_in[6];
    const float* bm1 = (const float*)d_in[7];
    const float* Wm2 = (const float*)d_in[8];
    const float* bm2 = (const float*)d_in[9];
    float* out = (float*)d_out;

    int n = in_sizes[0] / 3;
    int E = in_sizes[1] / 2;
    int nb = (n + SCAN_BS - 1) / SCAN_BS;
    int E8 = E >> 3;
    int edgeThreads = E8 + (E - E8 * 8);

    static void* deg_ptr = nullptr;
    static int attr_set = 0;
    if (!attr_set) {
        cudaFuncSetAttribute(k_mlp, cudaFuncAttributeMaxDynamicSharedMemorySize,
                             SMEM_MLP_FLOATS * (int)sizeof(float));
        cudaGetSymbolAddress(&deg_ptr, g_deg);
        attr_set = 1;
    }

    // CSR build
    cudaMemsetAsync(deg_ptr, 0, n * sizeof(int));
    k_deg_rank<<<(edgeThreads + 255) / 256, 256>>>(ei, E);
    k_scan<<<nb, SCAN_BS>>>(n, nb);
    k_scatter<<<(edgeThreads + 255) / 256, 256>>>(ei, E);

    // layer 1
    k_hw1<<<((n + 1) * 32 + 255) / 256, 256>>>(x, W1, n);
    int aggr_blocks = (n * 32 + 255) / 256;
    k_aggr<<<aggr_blocks, 256>>>(n);

    // layer 2
    k_gcn_gemm64<<<(n + 31) / 32, 256>>>(b1, W2, n);
    k_aggr<<<aggr_blocks, 256>>>(n);

    // fused MLP + softmax (32 rows/block, dynamic smem)
    k_mlp<<<(n + 31) / 32, 256, SMEM_MLP_FLOATS * (int)sizeof(float)>>>(
        b2, Wm1, bm1, Wm2, bm2, out, n);
}

// round 10
// speedup vs baseline: 1.0190x; 1.0190x over previous
#include <cuda_runtime.h>
#include <cuda_fp16.h>
#include <math.h>

#define NMAX 100000
#define EMAX 3200000
#define CSRMAX (EMAX + 3 * NMAX + 8)
#define HID  64
#define MHID 128
#define KOUT 15
#define SCAN_BS 1024
#define NBMAX ((NMAX + SCAN_BS - 1) / SCAN_BS)

// ---- device-global scratch (no allocations allowed) ----
__device__ __half g_ah[(NMAX + 1) * HID];  // fp16 pre-scaled messages; row n = zeros
__device__ float  g_b[NMAX * HID];         // aggregated output / GEMM input (fp32)
__device__ float  g_dis[NMAX];             // (deg+1)^{-1/2}
__device__ int    g_deg[NMAX];
__device__ int    g_off[NMAX + 1];         // CSR row offsets (padded to x4)
__device__ int    g_cur[NMAX];             // scatter cursors
__device__ int    g_csr[CSRMAX];           // CSR src indices (padded with n)
__device__ int    g_bsum[NBMAX];
__device__ int    g_bar;                   // device-wide barrier counter

__device__ __forceinline__ float eluf(float v) { return v > 0.f ? v : expm1f(v); }

__device__ __forceinline__ float4 h4tof4(uint2 v) {
    float2 a = __half22float2(*reinterpret_cast<__half2*>(&v.x));
    float2 b = __half22float2(*reinterpret_cast<__half2*>(&v.y));
    return make_float4(a.x, a.y, b.x, b.y);
}

// ---------------------------------------------------------------- degrees
__global__ void k_deg_edge(const int* __restrict__ ei, int E) {
    int t = blockIdx.x * blockDim.x + threadIdx.x;
    if (t == 0) g_bar = 0;                 // reset scan barrier for this launch
    int E8 = E >> 3;
    if (t < E8) {
        int4 d0 = reinterpret_cast<const int4*>(ei + E)[2 * t];
        int4 d1 = reinterpret_cast<const int4*>(ei + E)[2 * t + 1];
        atomicAdd(&g_deg[d0.x], 1); atomicAdd(&g_deg[d0.y], 1);
        atomicAdd(&g_deg[d0.z], 1); atomicAdd(&g_deg[d0.w], 1);
        atomicAdd(&g_deg[d1.x], 1); atomicAdd(&g_deg[d1.y], 1);
        atomicAdd(&g_deg[d1.z], 1); atomicAdd(&g_deg[d1.w], 1);
    } else {
        int e = E8 * 8 + (t - E8);
        if (e < E) atomicAdd(&g_deg[ei[E + e]], 1);
    }
}

// ---------------- fused exclusive scan + offsets/dis/cursor/dummy fill
__global__ void k_scan(int n, int nb) {
    __shared__ int s[SCAN_BS];
    int t = threadIdx.x;
    int b = blockIdx.x;
    int i = b * SCAN_BS + t;
    int deg = (i < n) ? g_deg[i] : 0;
    int pdeg = (deg + 3) & ~3;
    int v = pdeg;
    s[t] = v;
    __syncthreads();
#pragma unroll
    for (int off = 1; off < SCAN_BS; off <<= 1) {
        int add = (t >= off) ? s[t - off] : 0;
        __syncthreads();
        s[t] += add;
        __syncthreads();
    }
    int exc = s[t] - v;

    if (t == 0) {
        g_bsum[b] = s[SCAN_BS - 1];
        __threadfence();
        atomicAdd(&g_bar, 1);
        while (atomicAdd(&g_bar, 0) < nb) __nanosleep(64);
    }
    __syncthreads();
    __threadfence();

    s[t] = (t < b) ? g_bsum[t] : 0;
    __syncthreads();
#pragma unroll
    for (int off = SCAN_BS / 2; off > 0; off >>= 1) {
        if (t < off) s[t] += s[t + off];
        __syncthreads();
    }
    int off = s[0] + exc;

    if (i < n) {
        g_off[i] = off;
        g_cur[i] = off;
        g_dis[i] = rsqrtf((float)(deg + 1));
        for (int j = deg; j < pdeg; j++) g_csr[off + j] = n;  // dummy -> zero row
        if (i == n - 1) g_off[n] = off + pdeg;
    }
}

// -------------------------------------------- scatter (16 edges / thread)
__global__ void k_scatter(const int* __restrict__ ei, int E) {
    int t = blockIdx.x * blockDim.x + threadIdx.x;
    int E16 = E >> 4;
    if (t < E16) {
#pragma unroll
        for (int q = 0; q < 4; q++) {
            int4 s = reinterpret_cast<const int4*>(ei)[4 * t + q];
            int4 d = reinterpret_cast<const int4*>(ei + E)[4 * t + q];
            g_csr[atomicAdd(&g_cur[d.x], 1)] = s.x;
            g_csr[atomicAdd(&g_cur[d.y], 1)] = s.y;
            g_csr[atomicAdd(&g_cur[d.z], 1)] = s.z;
            g_csr[atomicAdd(&g_cur[d.w], 1)] = s.w;
        }
    } else {
        int e = E16 * 16 + (t - E16);
        if (e < E) g_csr[atomicAdd(&g_cur[ei[E + e]], 1)] = ei[e];
    }
}

// ------------------------------------------- layer-1 input GEMM (3 -> 64)
__global__ void k_hw1(const float* __restrict__ x, const float* __restrict__ W1, int n) {
    int idx = blockIdx.x * blockDim.x + threadIdx.x;   // over (n+1)*32
    if (idx >= (n + 1) * 32) return;
    int i = idx >> 5, f = (idx & 31) * 2;
    __half2* a2 = reinterpret_cast<__half2*>(g_ah);
    if (i == n) { a2[idx] = __floats2half2_rn(0.f, 0.f); return; }
    float x0 = x[i * 3 + 0], x1 = x[i * 3 + 1], x2 = x[i * 3 + 2];
    float d = g_dis[i];
    float v0 = (x0 * W1[f]     + x1 * W1[HID + f]     + x2 * W1[2 * HID + f]) * d;
    float v1 = (x0 * W1[f + 1] + x1 * W1[HID + f + 1] + x2 * W1[2 * HID + f + 1]) * d;
    a2[idx] = __floats2half2_rn(v0, v1);
}

// --------------------------------------------- CSR aggregation (hot, x2)
// warp per node; paired gathers; HADD2 4-term chunks (R8 form).
__global__ void k_aggr(int n) {
    int gw = (blockIdx.x * blockDim.x + threadIdx.x) >> 5;
    if (gw >= n) return;
    int lane = threadIdx.x & 31;
    const uint2* __restrict__ ah4 = reinterpret_cast<const uint2*>(g_ah);
    int half_ = lane >> 4;
    int fo = lane & 15;

    float4 acc = make_float4(0.f, 0.f, 0.f, 0.f);
    if (half_ == 0) acc = h4tof4(ah4[gw * 16 + fo]);   // self loop (fp32)

    int j = g_off[gw];
    int end = g_off[gw + 1];
    for (; j + 8 <= end; j += 8) {
        int4 i0 = *reinterpret_cast<const int4*>(&g_csr[j]);
        int4 i1 = *reinterpret_cast<const int4*>(&g_csr[j + 4]);
        int sA = half_ ? i0.y : i0.x;
        int sB = half_ ? i0.w : i0.z;
        int sC = half_ ? i1.y : i1.x;
        int sD = half_ ? i1.w : i1.z;
        uint2 vA = ah4[sA * 16 + fo];
        uint2 vB = ah4[sB * 16 + fo];
        uint2 vC = ah4[sC * 16 + fo];
        uint2 vD = ah4[sD * 16 + fo];
        __half2 p0 = __hadd2(__hadd2(*reinterpret_cast<__half2*>(&vA.x),
                                     *reinterpret_cast<__half2*>(&vB.x)),
                             __hadd2(*reinterpret_cast<__half2*>(&vC.x),
                                     *reinterpret_cast<__half2*>(&vD.x)));
        __half2 p1 = __hadd2(__hadd2(*reinterpret_cast<__half2*>(&vA.y),
                                     *reinterpret_cast<__half2*>(&vB.y)),
                             __hadd2(*reinterpret_cast<__half2*>(&vC.y),
                                     *reinterpret_cast<__half2*>(&vD.y)));
        float2 f0 = __half22float2(p0);
        float2 f1 = __half22float2(p1);
        acc.x += f0.x; acc.y += f0.y; acc.z += f1.x; acc.w += f1.y;
    }
    if (j < end) {
        int4 i0 = *reinterpret_cast<const int4*>(&g_csr[j]);
        int sA = half_ ? i0.y : i0.x;
        int sB = half_ ? i0.w : i0.z;
        uint2 vA = ah4[sA * 16 + fo];
        uint2 vB = ah4[sB * 16 + fo];
        __half2 p0 = __hadd2(*reinterpret_cast<__half2*>(&vA.x),
                             *reinterpret_cast<__half2*>(&vB.x));
        __half2 p1 = __hadd2(*reinterpret_cast<__half2*>(&vA.y),
                             *reinterpret_cast<__half2*>(&vB.y));
        float2 f0 = __half22float2(p0);
        float2 f1 = __half22float2(p1);
        acc.x += f0.x; acc.y += f0.y; acc.z += f1.x; acc.w += f1.y;
    }
    acc.x += __shfl_down_sync(0xffffffffu, acc.x, 16);
    acc.y += __shfl_down_sync(0xffffffffu, acc.y, 16);
    acc.z += __shfl_down_sync(0xffffffffu, acc.z, 16);
    acc.w += __shfl_down_sync(0xffffffffu, acc.w, 16);

    if (lane < 16) {
        float d = g_dis[gw];
        *reinterpret_cast<float4*>(&g_b[gw * HID + lane * 4]) =
            make_float4(acc.x * d, acc.y * d, acc.z * d, acc.w * d);
    }
}

// ---------------------------------------- layer-2 GEMM: elu(g_b+b1) @ W2
__global__ void k_gcn_gemm64(const float* __restrict__ bias,
                             const float* __restrict__ W, int n) {
    __shared__ float As[32][HID];
    __shared__ float Ws[HID * HID];
    int tid = threadIdx.x;
    int row0 = blockIdx.x * 32;

    for (int i = tid; i < HID * HID; i += 256) Ws[i] = W[i];
    for (int i = tid; i < 32 * HID; i += 256) {
        int r = i >> 6, k = i & 63;
        int row = row0 + r;
        As[r][k] = (row < n) ? eluf(g_b[row * HID + k] + bias[k]) : 0.f;
    }
    __syncthreads();

    int fx = (tid & 15) * 4;
    int n0 = (tid >> 4) * 2;
    float4 a0c = make_float4(0.f, 0.f, 0.f, 0.f);
    float4 a1c = make_float4(0.f, 0.f, 0.f, 0.f);
#pragma unroll 16
    for (int k = 0; k < HID; k++) {
        float4 w = *reinterpret_cast<const float4*>(&Ws[k * HID + fx]);
        float a0 = As[n0][k], a1 = As[n0 + 1][k];
        a0c.x += a0 * w.x; a0c.y += a0 * w.y; a0c.z += a0 * w.z; a0c.w += a0 * w.w;
        a1c.x += a1 * w.x; a1c.y += a1 * w.y; a1c.z += a1 * w.z; a1c.w += a1 * w.w;
    }
#pragma unroll
    for (int r = 0; r < 2; r++) {
        int row = row0 + n0 + r;
        if (row >= n) continue;
        float d = g_dis[row];
        float4 acc = r ? a1c : a0c;
        __half2* a2 = reinterpret_cast<__half2*>(g_ah);
        a2[row * 32 + (fx >> 1)]     = __floats2half2_rn(acc.x * d, acc.y * d);
        a2[row * 32 + (fx >> 1) + 1] = __floats2half2_rn(acc.z * d, acc.w * d);
    }
}

// ---------------- fused MLP (32 rows/block, dynamic smem) + softmax
#define SMEM_MLP_FLOATS (32 * HID + HID * MHID + 32 * MHID + MHID * KOUT + KOUT)
__global__ void k_mlp(const float* __restrict__ b2,
                      const float* __restrict__ Wm1,
                      const float* __restrict__ bm1,
                      const float* __restrict__ Wm2,
                      const float* __restrict__ bm2,
                      float* __restrict__ out, int n) {
    extern __shared__ float sm[];
    float* As  = sm;
    float* Ws  = As + 32 * HID;
    float* Hs  = Ws + HID * MHID;
    float* W2s = Hs + 32 * MHID;
    float* b2s = W2s + MHID * KOUT;
    int tid = threadIdx.x;
    int row0 = blockIdx.x * 32;

    for (int i = tid; i < HID * MHID; i += 256) Ws[i] = Wm1[i];
    for (int i = tid; i < MHID * KOUT; i += 256) W2s[i] = Wm2[i];
    if (tid < KOUT) b2s[tid] = bm2[tid];
    for (int i = tid; i < 32 * HID; i += 256) {
        int r = i >> 6, k = i & 63;
        int row = row0 + r;
        As[i] = (row < n) ? eluf(g_b[row * HID + k] + b2[k]) : 0.f;
    }
    __syncthreads();

    {
        int fx = (tid & 31) * 4;
        int r0 = (tid >> 5) * 4;
        float4 a0 = make_float4(0.f, 0.f, 0.f, 0.f);
        float4 a1 = make_float4(0.f, 0.f, 0.f, 0.f);
        float4 a2 = make_float4(0.f, 0.f, 0.f, 0.f);
        float4 a3 = make_float4(0.f, 0.f, 0.f, 0.f);
#pragma unroll 8
        for (int k = 0; k < HID; k++) {
            float4 w = *reinterpret_cast<const float4*>(&Ws[k * MHID + fx]);
            float v0 = As[(r0 + 0) * HID + k];
            float v1 = As[(r0 + 1) * HID + k];
            float v2 = As[(r0 + 2) * HID + k];
            float v3 = As[(r0 + 3) * HID + k];
            a0.x += v0 * w.x; a0.y += v0 * w.y; a0.z += v0 * w.z; a0.w += v0 * w.w;
            a1.x += v1 * w.x; a1.y += v1 * w.y; a1.z += v1 * w.z; a1.w += v1 * w.w;
            a2.x += v2 * w.x; a2.y += v2 * w.y; a2.z += v2 * w.z; a2.w += v2 * w.w;
            a3.x += v3 * w.x; a3.y += v3 * w.y; a3.z += v3 * w.z; a3.w += v3 * w.w;
        }
        float4 bb = *reinterpret_cast<const float4*>(&bm1[fx]);
        *reinterpret_cast<float4*>(&Hs[(r0 + 0) * MHID + fx]) =
            make_float4(eluf(a0.x + bb.x), eluf(a0.y + bb.y), eluf(a0.z + bb.z), eluf(a0.w + bb.w));
        *reinterpret_cast<float4*>(&Hs[(r0 + 1) * MHID + fx]) =
            make_float4(eluf(a1.x + bb.x), eluf(a1.y + bb.y), eluf(a1.z + bb.z), eluf(a1.w + bb.w));
        *reinterpret_cast<float4*>(&Hs[(r0 + 2) * MHID + fx]) =
            make_float4(eluf(a2.x + bb.x), eluf(a2.y + bb.y), eluf(a2.z + bb.z), eluf(a2.w + bb.w));
        *reinterpret_cast<float4*>(&Hs[(r0 + 3) * MHID + fx]) =
            make_float4(eluf(a3.x + bb.x), eluf(a3.y + bb.y), eluf(a3.z + bb.z), eluf(a3.w + bb.w));
    }
    __syncthreads();

    int wid = tid >> 5;
    int lane = tid & 31;
#pragma unroll
    for (int rr = 0; rr < 4; rr++) {
        int r = wid * 4 + rr;
        int row = row0 + r;
        float p[KOUT];
#pragma unroll
        for (int c = 0; c < KOUT; c++) p[c] = 0.f;
#pragma unroll
        for (int jj = 0; jj < 4; jj++) {
            int k = lane + 32 * jj;
            float hv = Hs[r * MHID + k];
#pragma unroll
            for (int c = 0; c < KOUT; c++) p[c] += hv * W2s[k * KOUT + c];
        }
#pragma unroll
        for (int off = 16; off > 0; off >>= 1)
#pragma unroll
            for (int c = 0; c < KOUT; c++)
                p[c] += __shfl_xor_sync(0xffffffffu, p[c], off);

        float mx = -1e30f;
#pragma unroll
        for (int c = 0; c < KOUT; c++) { p[c] += b2s[c]; mx = fmaxf(mx, p[c]); }
        float s = 0.f;
#pragma unroll
        for (int c = 0; c < KOUT; c++) { p[c] = expf(p[c] - mx); s += p[c]; }
        float inv = 1.f / s;
        if (row < n && lane < KOUT) out[row * KOUT + lane] = p[lane] * inv;
    }
}

// ---------------------------------------------------------------- launch
extern "C" void kernel_launch(void* const* d_in, const int* in_sizes, int n_in,
                              void* d_out, int out_size) {
    const float* x   = (const float*)d_in[0];
    const int*   ei  = (const int*)  d_in[1];
    const float* W1  = (const float*)d_in[2];
    const float* b1  = (const float*)d_in[3];
    const float* W2  = (const float*)d_in[4];
    const float* b2  = (const float*)d_in[5];
    const float* Wm1 = (const float*)d_in[6];
    const float* bm1 = (const float*)d_in[7];
    const float* Wm2 = (const float*)d_in[8];
    const float* bm2 = (const float*)d_in[9];
    float* out = (float*)d_out;

    int n = in_sizes[0] / 3;
    int E = in_sizes[1] / 2;
    int nb = (n + SCAN_BS - 1) / SCAN_BS;
    int E8 = E >> 3;
    int degThreads = E8 + (E - E8 * 8);
    int E16 = E >> 4;
    int scatThreads = E16 + (E - E16 * 16);

    static void* deg_ptr = nullptr;
    static cudaStream_t s2 = nullptr;
    static cudaEvent_t evFork = nullptr, evJoin = nullptr;
    static int init_done = 0;
    if (!init_done) {
        cudaFuncSetAttribute(k_mlp, cudaFuncAttributeMaxDynamicSharedMemorySize,
                             SMEM_MLP_FLOATS * (int)sizeof(float));
        cudaGetSymbolAddress(&deg_ptr, g_deg);
        cudaStreamCreateWithFlags(&s2, cudaStreamNonBlocking);
        cudaEventCreateWithFlags(&evFork, cudaEventDisableTiming);
        cudaEventCreateWithFlags(&evJoin, cudaEventDisableTiming);
        init_done = 1;
    }

    // CSR build front half (main stream)
    cudaMemsetAsync(deg_ptr, 0, n * sizeof(int));
    k_deg_edge<<<(degThreads + 255) / 256, 256>>>(ei, E);
    k_scan<<<nb, SCAN_BS>>>(n, nb);

    // fork: scatter on s2, hw1 on main stream (independent)
    cudaEventRecord(evFork, 0);
    cudaStreamWaitEvent(s2, evFork, 0);
    k_scatter<<<(scatThreads + 255) / 256, 256, 0, s2>>>(ei, E);
    k_hw1<<<((n + 1) * 32 + 255) / 256, 256>>>(x, W1, n);
    cudaEventRecord(evJoin, s2);
    cudaStreamWaitEvent(0, evJoin, 0);

    // layer 1 aggregation
    int aggr_blocks = (n * 32 + 255) / 256;
    k_aggr<<<aggr_blocks, 256>>>(n);

    // layer 2
    k_gcn_gemm64<<<(n + 31) / 32, 256>>>(b1, W2, n);
    k_aggr<<<aggr_blocks, 256>>>(n);

    // fused MLP + softmax
    k_mlp<<<(n + 31) / 32, 256, SMEM_MLP_FLOATS * (int)sizeof(float)>>>(
        b2, Wm1, bm1, Wm2, bm2, out, n);
}